// round 13
// baseline (speedup 1.0000x reference)
#include <cuda_runtime.h>
#include <math.h>

#define N     8192
#define FIN   256
#define FOUT  64
#define RPB   16     // rows per block in main A-scan kernel
#define NBKT  8192   // value buckets for the sort
#define NBLK4 128    // chunks in K4 scan
#define CHUNK 64     // ranks per chunk (NBLK4*CHUNK == N)

// ---------------- scratch (device globals; no allocations) ----------------
__device__ __align__(16) float g_Wh[N * FOUT];       // H @ W + bW
__device__ __align__(16) float g_s[N];               // s_src + a_b
__device__ __align__(16) float g_t[N];               // s_tar
__device__ __align__(16) float g_u[N];               // exp(t)
__device__ __align__(16) float g_v[N];               // exp(0.01 t)
__device__ __align__(16) float g_ts[N];              // sorted t (ascending)
__device__ __align__(16) int   g_perm[N];            // argsort of t
__device__ __align__(16) int   g_kidx[N];            // lower_bound(ts, -s_i)
__device__ __align__(16) float g_Pu[(N + 1) * FOUT]; // chunk-local exclusive prefix of u*Wh
__device__ __align__(16) float g_Pv[(N + 1) * FOUT]; // chunk-local exclusive prefix of v*Wh
__device__ __align__(16) float g_blkU[(NBLK4 + 1) * FOUT]; // cross-chunk exclusive offsets (+ total)
__device__ __align__(16) float g_blkV[(NBLK4 + 1) * FOUT];
// sort scratch
__device__ float g_tmin, g_tmax;
__device__ __align__(16) int g_bcnt[NBKT];
__device__ __align__(16) int g_boff[NBKT + 1];
__device__ __align__(16) int g_bfill[NBKT];
__device__ __align__(16) int g_bkt[N];

// ---------------- K1: Wh = H @ W + bW  (fp32 tiled GEMM) ----------------
__global__ void k1_gemm(const float* __restrict__ H,
                        const float* __restrict__ W,
                        const float* __restrict__ bW) {
    __shared__ float As[16][72];
    __shared__ float Bs[16][64];
    const int tid = threadIdx.x;          // 256 threads
    const int tx = tid & 15, ty = tid >> 4;
    const int m0 = blockIdx.x * 64;

    float acc[4][4];
#pragma unroll
    for (int r = 0; r < 4; r++)
#pragma unroll
        for (int c = 0; c < 4; c++) acc[r][c] = 0.f;

    for (int k0 = 0; k0 < FIN; k0 += 16) {
#pragma unroll
        for (int e = 0; e < 4; e++) {
            int li = tid + e * 256;
            int m = li >> 4, kk = li & 15;
            As[kk][m] = H[(m0 + m) * FIN + k0 + kk];
        }
#pragma unroll
        for (int e = 0; e < 4; e++) {
            int li = tid + e * 256;
            int kk = li >> 6, n = li & 63;
            Bs[kk][n] = W[(k0 + kk) * FOUT + n];
        }
        __syncthreads();
#pragma unroll
        for (int kk = 0; kk < 16; kk++) {
            float4 a4 = *(const float4*)&As[kk][ty * 4];
            float4 b4 = *(const float4*)&Bs[kk][tx * 4];
            float av[4] = {a4.x, a4.y, a4.z, a4.w};
            float bv[4] = {b4.x, b4.y, b4.z, b4.w};
#pragma unroll
            for (int r = 0; r < 4; r++)
#pragma unroll
                for (int c = 0; c < 4; c++) acc[r][c] += av[r] * bv[c];
        }
        __syncthreads();
    }
#pragma unroll
    for (int r = 0; r < 4; r++) {
        int m = m0 + ty * 4 + r;
#pragma unroll
        for (int c = 0; c < 4; c++) {
            int n = tx * 4 + c;
            g_Wh[m * FOUT + n] = acc[r][c] + bW[n];
        }
    }
}

// ---------------- K2: scores s, t and per-node exp tables u, v ----------------
__global__ void k2_scores(const float* __restrict__ a_w,
                          const float* __restrict__ a_b) {
    const int i = blockIdx.x * 8 + (threadIdx.x >> 5);  // one warp per row
    const int lane = threadIdx.x & 31;
    float w0 = g_Wh[i * FOUT + lane];
    float w1 = g_Wh[i * FOUT + 32 + lane];
    float ps = w0 * a_w[lane] + w1 * a_w[32 + lane];
    float pt = w0 * a_w[64 + lane] + w1 * a_w[96 + lane];
#pragma unroll
    for (int o = 16; o; o >>= 1) {
        ps += __shfl_xor_sync(0xFFFFFFFFu, ps, o);
        pt += __shfl_xor_sync(0xFFFFFFFFu, pt, o);
    }
    if (lane == 0) {
        g_s[i] = ps + a_b[0];
        g_t[i] = pt;
        g_u[i] = expf(pt);
        g_v[i] = expf(0.01f * pt);
    }
}

// ---------------- Sort stage 1: min/max of t + zero bucket counts ----------------
__global__ void ks_minmax() {
    __shared__ float smn[32], smx[32];
    const int tid = threadIdx.x;  // 1024
    float mn = 3.4e38f, mx = -3.4e38f;
#pragma unroll
    for (int e = 0; e < N / 1024; e++) {
        float v = g_t[tid + e * 1024];
        mn = fminf(mn, v);
        mx = fmaxf(mx, v);
    }
#pragma unroll
    for (int o = 16; o; o >>= 1) {
        mn = fminf(mn, __shfl_xor_sync(0xFFFFFFFFu, mn, o));
        mx = fmaxf(mx, __shfl_xor_sync(0xFFFFFFFFu, mx, o));
    }
    if ((tid & 31) == 0) { smn[tid >> 5] = mn; smx[tid >> 5] = mx; }
    __syncthreads();
    if (tid < 32) {
        mn = smn[tid]; mx = smx[tid];
#pragma unroll
        for (int o = 16; o; o >>= 1) {
            mn = fminf(mn, __shfl_xor_sync(0xFFFFFFFFu, mn, o));
            mx = fmaxf(mx, __shfl_xor_sync(0xFFFFFFFFu, mx, o));
        }
        if (tid == 0) { g_tmin = mn; g_tmax = mx; }
    }
#pragma unroll
    for (int e = 0; e < NBKT / 1024; e++) g_bcnt[tid + e * 1024] = 0;
}

// ---------------- Sort stage 2: histogram ----------------
__global__ void ks_hist() {
    const int i = blockIdx.x * 256 + threadIdx.x;
    const float tmin = g_tmin, tmax = g_tmax;
    const float range = tmax - tmin;
    const float inv = (range > 0.f) ? (float)(NBKT - 1) / range : 0.f;
    float t = g_t[i];
    int b = (int)((t - tmin) * inv);
    b = max(0, min(NBKT - 1, b));
    g_bkt[i] = b;
    atomicAdd(&g_bcnt[b], 1);
}

// ---------------- Sort stage 3: exclusive scan of bucket counts ----------------
__global__ void ks_scan() {
    __shared__ int ssum[1024];
    const int tid = threadIdx.x;  // 1024
    const int base = tid * (NBKT / 1024);   // 8 buckets each
    int c[NBKT / 1024];
    int sum = 0;
#pragma unroll
    for (int e = 0; e < NBKT / 1024; e++) { c[e] = g_bcnt[base + e]; sum += c[e]; }
    ssum[tid] = sum;
    __syncthreads();
    // Hillis-Steele inclusive over 1024 partials
    for (int off = 1; off < 1024; off <<= 1) {
        int x = (tid >= off) ? ssum[tid - off] : 0;
        __syncthreads();
        ssum[tid] += x;
        __syncthreads();
    }
    int run = ssum[tid] - sum;  // exclusive
#pragma unroll
    for (int e = 0; e < NBKT / 1024; e++) {
        g_boff[base + e] = run;
        g_bfill[base + e] = run;
        run += c[e];
    }
    if (tid == 1023) g_boff[NBKT] = N;
}

// ---------------- Sort stage 4: scatter into buckets ----------------
__global__ void ks_scatter() {
    const int i = blockIdx.x * 256 + threadIdx.x;
    int b = g_bkt[i];
    int pos = atomicAdd(&g_bfill[b], 1);
    g_ts[pos] = g_t[i];
    g_perm[pos] = i;
}

// ---------------- Sort stage 5: per-bucket insertion sort ----------------
__global__ void ks_insert() {
    const int b = blockIdx.x * 256 + threadIdx.x;
    const int start = g_boff[b];
    const int end = g_boff[b + 1];
    for (int x = start + 1; x < end; x++) {
        float kv = g_ts[x];
        int kp = g_perm[x];
        int y = x - 1;
        while (y >= start && g_ts[y] > kv) {
            g_ts[y + 1] = g_ts[y];
            g_perm[y + 1] = g_perm[y];
            y--;
        }
        g_ts[y + 1] = kv;
        g_perm[y + 1] = kp;
    }
}

// ---------------- K3b: k_i = lower_bound(ts, -s_i), SMEM-staged ----------------
__global__ void k3b_kidx() {
    __shared__ float sts[N];  // 32KB
    const int tid = threadIdx.x;  // 256
    for (int idx = tid; idx < N / 4; idx += 256)
        ((float4*)sts)[idx] = ((const float4*)g_ts)[idx];
    __syncthreads();
    const int i = blockIdx.x * 256 + tid;
    const float thr = -g_s[i];
    int lo = 0, hi = N;
    while (lo < hi) {
        int mid = (lo + hi) >> 1;
        if (sts[mid] < thr) lo = mid + 1; else hi = mid;
    }
    g_kidx[i] = lo;
}

// ---------------- K4a: chunk-local exclusive prefixes (coalesced) ----------------
__global__ void k4a_local() {
    __shared__ int   sp[CHUNK];
    __shared__ float su[CHUNK], sv[CHUNK];
    const int tid = threadIdx.x;          // 64 threads, tid == feature
    const int r0 = blockIdx.x * CHUNK;
    {
        int p = g_perm[r0 + tid];
        sp[tid] = p;
        su[tid] = g_u[p];
        sv[tid] = g_v[p];
    }
    __syncthreads();
    float ru = 0.f, rv = 0.f;
#pragma unroll 8
    for (int e = 0; e < CHUNK; e++) {
        int p = sp[e];
        float wh = __ldg(&g_Wh[p * FOUT + tid]);
        g_Pu[(r0 + e) * FOUT + tid] = ru;
        g_Pv[(r0 + e) * FOUT + tid] = rv;
        ru += su[e] * wh;
        rv += sv[e] * wh;
    }
    g_blkU[blockIdx.x * FOUT + tid] = ru;   // raw chunk totals (scanned by k4b)
    g_blkV[blockIdx.x * FOUT + tid] = rv;
}

// ---------------- K4b: cross-chunk exclusive scan (in SMEM) ----------------
__global__ void k4b_scan() {
    __shared__ float s[NBLK4 * FOUT];  // 32KB
    const int tid = threadIdx.x;       // 1024
#pragma unroll
    for (int pass = 0; pass < 2; pass++) {
        float* arr = pass ? g_blkV : g_blkU;
#pragma unroll
        for (int e = 0; e < (NBLK4 * FOUT) / 1024; e++)
            s[tid + e * 1024] = arr[tid + e * 1024];
        __syncthreads();
        // inclusive scan along chunk axis (stride FOUT)
        for (int off = 1; off < NBLK4; off <<= 1) {
            float tmp[(NBLK4 * FOUT) / 1024];
#pragma unroll
            for (int e = 0; e < (NBLK4 * FOUT) / 1024; e++) {
                int idx = tid + e * 1024;
                int b = idx >> 6;
                tmp[e] = (b >= off) ? s[idx - off * FOUT] : 0.f;
            }
            __syncthreads();
#pragma unroll
            for (int e = 0; e < (NBLK4 * FOUT) / 1024; e++)
                s[tid + e * 1024] += tmp[e];
            __syncthreads();
        }
        // write exclusive offsets + grand total; zero virtual row N of P
#pragma unroll
        for (int e = 0; e < (NBLK4 * FOUT) / 1024; e++) {
            int idx = tid + e * 1024;
            int b = idx >> 6;
            arr[idx] = (b > 0) ? s[idx - FOUT] : 0.f;
        }
        if (tid < FOUT) {
            arr[NBLK4 * FOUT + tid] = s[(NBLK4 - 1) * FOUT + tid];
            if (pass == 0) g_Pu[N * FOUT + tid] = 0.f;
            else           g_Pv[N * FOUT + tid] = 0.f;
        }
        __syncthreads();
    }
}

// ---------------- K5: A-masked denominator scan + output ----------------
__global__ void k5_main(const int* __restrict__ A, float* __restrict__ out) {
    extern __shared__ float smem[];
    float4* t4 = (float4*)smem;
    float4* u4 = t4 + N / 4;
    float4* v4 = u4 + N / 4;
    __shared__ float red_u[RPB * 8], red_v[RPB * 8];

    const int tid = threadIdx.x;   // 256 threads, 8 warps
    const int wid = tid >> 5;
    const int lane = tid & 31;

    for (int idx = tid; idx < N / 4; idx += 256) {
        t4[idx] = ((const float4*)g_t)[idx];
        u4[idx] = ((const float4*)g_u)[idx];
        v4[idx] = ((const float4*)g_v)[idx];
    }
    __syncthreads();

    const int i0 = blockIdx.x * RPB;
    for (int r = 0; r < RPB; r++) {
        const int i = i0 + r;
        const float thr = -g_s[i];
        const int4* Arow = (const int4*)(A + (long long)i * N);

        int4 a[8];
#pragma unroll
        for (int c = 0; c < 8; c++) a[c] = __ldcs(&Arow[tid + c * 256]);

        float au = 0.f, av = 0.f;
#pragma unroll
        for (int c = 0; c < 8; c++) {
            const int idx = tid + c * 256;
            float4 tt = t4[idx];
            float4 uu = u4[idx];
            float4 vv = v4[idx];
            if (a[c].x) { if (tt.x >= thr) au += uu.x; else av += vv.x; }
            if (a[c].y) { if (tt.y >= thr) au += uu.y; else av += vv.y; }
            if (a[c].z) { if (tt.z >= thr) au += uu.z; else av += vv.z; }
            if (a[c].w) { if (tt.w >= thr) au += uu.w; else av += vv.w; }
        }
#pragma unroll
        for (int o = 16; o; o >>= 1) {
            au += __shfl_xor_sync(0xFFFFFFFFu, au, o);
            av += __shfl_xor_sync(0xFFFFFFFFu, av, o);
        }
        if (lane == 0) { red_u[r * 8 + wid] = au; red_v[r * 8 + wid] = av; }
    }
    __syncthreads();

    for (int rr = tid >> 6; rr < RPB; rr += 4) {
        const int i = i0 + rr;
        const int f = tid & 63;
        float au = 0.f, av = 0.f;
#pragma unroll
        for (int w = 0; w < 8; w++) { au += red_u[rr * 8 + w]; av += red_v[rr * 8 + w]; }
        const float s = g_s[i];
        const float eu = expf(s);
        const float ev = expf(0.01f * s);
        const float denom = eu * au + ev * av;
        const int k = g_kidx[i];
        const float Tu = g_blkU[NBLK4 * FOUT + f];
        const float pu = g_Pu[k * FOUT + f] + g_blkU[(k >> 6) * FOUT + f];
        const float pv = g_Pv[k * FOUT + f] + g_blkV[(k >> 6) * FOUT + f];
        const float num = eu * (Tu - pu) + ev * pv;
        const float x = num / denom;
        out[i * FOUT + f] = 1.f / (1.f + expf(-x));
    }
}

// ---------------- launch ----------------
extern "C" void kernel_launch(void* const* d_in, const int* in_sizes, int n_in,
                              void* d_out, int out_size) {
    (void)in_sizes; (void)n_in; (void)out_size;
    const float* H   = (const float*)d_in[0];
    const int*   A   = (const int*)d_in[1];
    const float* W   = (const float*)d_in[2];
    const float* bW  = (const float*)d_in[3];
    const float* a_w = (const float*)d_in[4];
    const float* a_b = (const float*)d_in[5];
    float* out = (float*)d_out;

    static const int MAIN_SMEM = 3 * N * (int)sizeof(float);  // 96 KB
    cudaFuncSetAttribute(k5_main, cudaFuncAttributeMaxDynamicSharedMemorySize, MAIN_SMEM);

    k1_gemm<<<N / 64, 256>>>(H, W, bW);
    k2_scores<<<N / 8, 256>>>(a_w, a_b);
    ks_minmax<<<1, 1024>>>();
    ks_hist<<<N / 256, 256>>>();
    ks_scan<<<1, 1024>>>();
    ks_scatter<<<N / 256, 256>>>();
    ks_insert<<<NBKT / 256, 256>>>();
    k3b_kidx<<<N / 256, 256>>>();
    k4a_local<<<NBLK4, CHUNK>>>();
    k4b_scan<<<1, 1024>>>();
    k5_main<<<N / RPB, 256, MAIN_SMEM>>>(A, out);
}

// round 14
// speedup vs baseline: 1.3169x; 1.3169x over previous
#include <cuda_runtime.h>
#include <math.h>

#define N     8192
#define FIN   256
#define FOUT  64
#define RPB   16     // rows per block in main A-scan kernel
#define NBKT  8192   // value buckets for the sort
#define NBLK4 128    // chunks in K4 scan
#define CHUNK 64     // ranks per chunk (NBLK4*CHUNK == N)

// ---------------- scratch (device globals; no allocations) ----------------
__device__ __align__(16) float g_Wh[N * FOUT];       // H @ W + bW
__device__ __align__(16) float g_s[N];               // s_src + a_b
__device__ __align__(16) float g_t[N];               // s_tar
__device__ __align__(16) float g_u[N];               // exp(t)
__device__ __align__(16) float g_v[N];               // exp(0.01 t)
__device__ __align__(16) float g_ts[N];              // sorted t (ascending)
__device__ __align__(16) int   g_perm[N];            // argsort of t
__device__ __align__(16) int   g_kidx[N];            // lower_bound(ts, -s_i)
__device__ __align__(16) float g_Pu[(N + 1) * FOUT]; // chunk-local exclusive prefix of u*Wh
__device__ __align__(16) float g_Pv[(N + 1) * FOUT]; // chunk-local exclusive prefix of v*Wh
__device__ __align__(16) float g_blkU[(NBLK4 + 1) * FOUT]; // cross-chunk exclusive offsets (+ total)
__device__ __align__(16) float g_blkV[(NBLK4 + 1) * FOUT];
// denominator chain outputs
__device__ __align__(16) float g_den[N];
__device__ __align__(16) float g_eu[N];
__device__ __align__(16) float g_ev[N];
// sort scratch
__device__ float g_tmin, g_tmax;
__device__ __align__(16) int g_bcnt[NBKT];
__device__ __align__(16) int g_boff[NBKT + 1];
__device__ __align__(16) int g_bfill[NBKT];
__device__ __align__(16) int g_bkt[N];

// ---------------- K1: Wh = H @ W + bW  + fused score epilogue ----------------
__global__ void k1_gemm(const float* __restrict__ H,
                        const float* __restrict__ W,
                        const float* __restrict__ bW,
                        const float* __restrict__ a_w,
                        const float* __restrict__ a_b) {
    __shared__ float As[16][72];
    __shared__ float Bs[16][64];
    const int tid = threadIdx.x;          // 256 threads
    const int tx = tid & 15, ty = tid >> 4;
    const int m0 = blockIdx.x * 64;

    float acc[4][4];
#pragma unroll
    for (int r = 0; r < 4; r++)
#pragma unroll
        for (int c = 0; c < 4; c++) acc[r][c] = 0.f;

    for (int k0 = 0; k0 < FIN; k0 += 16) {
#pragma unroll
        for (int e = 0; e < 4; e++) {
            int li = tid + e * 256;
            int m = li >> 4, kk = li & 15;
            As[kk][m] = H[(m0 + m) * FIN + k0 + kk];
        }
#pragma unroll
        for (int e = 0; e < 4; e++) {
            int li = tid + e * 256;
            int kk = li >> 6, n = li & 63;
            Bs[kk][n] = W[(k0 + kk) * FOUT + n];
        }
        __syncthreads();
#pragma unroll
        for (int kk = 0; kk < 16; kk++) {
            float4 a4 = *(const float4*)&As[kk][ty * 4];
            float4 b4 = *(const float4*)&Bs[kk][tx * 4];
            float av[4] = {a4.x, a4.y, a4.z, a4.w};
            float bv[4] = {b4.x, b4.y, b4.z, b4.w};
#pragma unroll
            for (int r = 0; r < 4; r++)
#pragma unroll
                for (int c = 0; c < 4; c++) acc[r][c] += av[r] * bv[c];
        }
        __syncthreads();
    }

    // load bias and score weights for this thread's 4 columns
    float bwc[4], a1c[4], a2c[4];
#pragma unroll
    for (int c = 0; c < 4; c++) {
        int n = tx * 4 + c;
        bwc[c] = bW[n];
        a1c[c] = a_w[n];          // source half
        a2c[c] = a_w[FOUT + n];   // target half
    }

    float wh[4][4];
#pragma unroll
    for (int r = 0; r < 4; r++) {
        int m = m0 + ty * 4 + r;
#pragma unroll
        for (int c = 0; c < 4; c++) {
            wh[r][c] = acc[r][c] + bwc[c];
            g_Wh[m * FOUT + tx * 4 + c] = wh[r][c];
        }
    }

    // fused score epilogue: reduce across the 16 tx lanes (consecutive lanes)
    const float ab = a_b[0];
#pragma unroll
    for (int r = 0; r < 4; r++) {
        float ps = 0.f, pt = 0.f;
#pragma unroll
        for (int c = 0; c < 4; c++) {
            ps += wh[r][c] * a1c[c];
            pt += wh[r][c] * a2c[c];
        }
#pragma unroll
        for (int o = 8; o; o >>= 1) {   // xor-reduce within 16-lane group
            ps += __shfl_xor_sync(0xFFFFFFFFu, ps, o);
            pt += __shfl_xor_sync(0xFFFFFFFFu, pt, o);
        }
        if (tx == 0) {
            int i = m0 + ty * 4 + r;
            g_s[i] = ps + ab;
            g_t[i] = pt;
            g_u[i] = expf(pt);
            g_v[i] = expf(0.01f * pt);
        }
    }
}

// ---------------- Sort stage 1: min/max of t + zero bucket counts ----------------
__global__ void ks_minmax() {
    __shared__ float smn[32], smx[32];
    const int tid = threadIdx.x;  // 1024
    float mn = 3.4e38f, mx = -3.4e38f;
#pragma unroll
    for (int e = 0; e < N / 1024; e++) {
        float v = g_t[tid + e * 1024];
        mn = fminf(mn, v);
        mx = fmaxf(mx, v);
    }
#pragma unroll
    for (int o = 16; o; o >>= 1) {
        mn = fminf(mn, __shfl_xor_sync(0xFFFFFFFFu, mn, o));
        mx = fmaxf(mx, __shfl_xor_sync(0xFFFFFFFFu, mx, o));
    }
    if ((tid & 31) == 0) { smn[tid >> 5] = mn; smx[tid >> 5] = mx; }
    __syncthreads();
    if (tid < 32) {
        mn = smn[tid]; mx = smx[tid];
#pragma unroll
        for (int o = 16; o; o >>= 1) {
            mn = fminf(mn, __shfl_xor_sync(0xFFFFFFFFu, mn, o));
            mx = fmaxf(mx, __shfl_xor_sync(0xFFFFFFFFu, mx, o));
        }
        if (tid == 0) { g_tmin = mn; g_tmax = mx; }
    }
#pragma unroll
    for (int e = 0; e < NBKT / 1024; e++) g_bcnt[tid + e * 1024] = 0;
}

// ---------------- Sort stage 2: histogram ----------------
__global__ void ks_hist() {
    const int i = blockIdx.x * 256 + threadIdx.x;
    const float tmin = g_tmin, tmax = g_tmax;
    const float range = tmax - tmin;
    const float inv = (range > 0.f) ? (float)(NBKT - 1) / range : 0.f;
    float t = g_t[i];
    int b = (int)((t - tmin) * inv);
    b = max(0, min(NBKT - 1, b));
    g_bkt[i] = b;
    atomicAdd(&g_bcnt[b], 1);
}

// ---------------- Sort stage 3: exclusive scan of bucket counts ----------------
__global__ void ks_scan() {
    __shared__ int ssum[1024];
    const int tid = threadIdx.x;  // 1024
    const int base = tid * (NBKT / 1024);   // 8 buckets each
    int c[NBKT / 1024];
    int sum = 0;
#pragma unroll
    for (int e = 0; e < NBKT / 1024; e++) { c[e] = g_bcnt[base + e]; sum += c[e]; }
    ssum[tid] = sum;
    __syncthreads();
    for (int off = 1; off < 1024; off <<= 1) {
        int x = (tid >= off) ? ssum[tid - off] : 0;
        __syncthreads();
        ssum[tid] += x;
        __syncthreads();
    }
    int run = ssum[tid] - sum;  // exclusive
#pragma unroll
    for (int e = 0; e < NBKT / 1024; e++) {
        g_boff[base + e] = run;
        g_bfill[base + e] = run;
        run += c[e];
    }
    if (tid == 1023) g_boff[NBKT] = N;
}

// ---------------- Sort stage 4: scatter into buckets ----------------
__global__ void ks_scatter() {
    const int i = blockIdx.x * 256 + threadIdx.x;
    int b = g_bkt[i];
    int pos = atomicAdd(&g_bfill[b], 1);
    g_ts[pos] = g_t[i];
    g_perm[pos] = i;
}

// ---------------- Sort stage 5: per-bucket insertion sort ----------------
__global__ void ks_insert() {
    const int b = blockIdx.x * 256 + threadIdx.x;
    const int start = g_boff[b];
    const int end = g_boff[b + 1];
    for (int x = start + 1; x < end; x++) {
        float kv = g_ts[x];
        int kp = g_perm[x];
        int y = x - 1;
        while (y >= start && g_ts[y] > kv) {
            g_ts[y + 1] = g_ts[y];
            g_perm[y + 1] = g_perm[y];
            y--;
        }
        g_ts[y + 1] = kv;
        g_perm[y + 1] = kp;
    }
}

// ---------------- K3b: k_i = lower_bound(ts, -s_i), SMEM-staged ----------------
__global__ void k3b_kidx() {
    __shared__ float sts[N];  // 32KB
    const int tid = threadIdx.x;  // 256
    for (int idx = tid; idx < N / 4; idx += 256)
        ((float4*)sts)[idx] = ((const float4*)g_ts)[idx];
    __syncthreads();
    const int i = blockIdx.x * 256 + tid;
    const float thr = -g_s[i];
    int lo = 0, hi = N;
    while (lo < hi) {
        int mid = (lo + hi) >> 1;
        if (sts[mid] < thr) lo = mid + 1; else hi = mid;
    }
    g_kidx[i] = lo;
}

// ---------------- K4a: chunk-local exclusive prefixes (coalesced) ----------------
__global__ void k4a_local() {
    __shared__ int   sp[CHUNK];
    __shared__ float su[CHUNK], sv[CHUNK];
    const int tid = threadIdx.x;          // 64 threads, tid == feature
    const int r0 = blockIdx.x * CHUNK;
    {
        int p = g_perm[r0 + tid];
        sp[tid] = p;
        su[tid] = g_u[p];
        sv[tid] = g_v[p];
    }
    __syncthreads();
    float ru = 0.f, rv = 0.f;
#pragma unroll 8
    for (int e = 0; e < CHUNK; e++) {
        int p = sp[e];
        float wh = __ldg(&g_Wh[p * FOUT + tid]);
        g_Pu[(r0 + e) * FOUT + tid] = ru;
        g_Pv[(r0 + e) * FOUT + tid] = rv;
        ru += su[e] * wh;
        rv += sv[e] * wh;
    }
    g_blkU[blockIdx.x * FOUT + tid] = ru;   // raw chunk totals (scanned by k4b)
    g_blkV[blockIdx.x * FOUT + tid] = rv;
}

// ---------------- K4b: cross-chunk exclusive scan (in SMEM) ----------------
__global__ void k4b_scan() {
    __shared__ float s[NBLK4 * FOUT];  // 32KB
    const int tid = threadIdx.x;       // 1024
#pragma unroll
    for (int pass = 0; pass < 2; pass++) {
        float* arr = pass ? g_blkV : g_blkU;
#pragma unroll
        for (int e = 0; e < (NBLK4 * FOUT) / 1024; e++)
            s[tid + e * 1024] = arr[tid + e * 1024];
        __syncthreads();
        for (int off = 1; off < NBLK4; off <<= 1) {
            float tmp[(NBLK4 * FOUT) / 1024];
#pragma unroll
            for (int e = 0; e < (NBLK4 * FOUT) / 1024; e++) {
                int idx = tid + e * 1024;
                int b = idx >> 6;
                tmp[e] = (b >= off) ? s[idx - off * FOUT] : 0.f;
            }
            __syncthreads();
#pragma unroll
            for (int e = 0; e < (NBLK4 * FOUT) / 1024; e++)
                s[tid + e * 1024] += tmp[e];
            __syncthreads();
        }
#pragma unroll
        for (int e = 0; e < (NBLK4 * FOUT) / 1024; e++) {
            int idx = tid + e * 1024;
            int b = idx >> 6;
            arr[idx] = (b > 0) ? s[idx - FOUT] : 0.f;
        }
        if (tid < FOUT) {
            arr[NBLK4 * FOUT + tid] = s[(NBLK4 - 1) * FOUT + tid];
            if (pass == 0) g_Pu[N * FOUT + tid] = 0.f;
            else           g_Pv[N * FOUT + tid] = 0.f;
        }
        __syncthreads();
    }
}

// ---------------- K5a: A-masked denominator scan (HBM-bound, overlaps chain B) ----------------
__global__ void k5a_den(const int* __restrict__ A) {
    extern __shared__ float smem[];
    float4* t4 = (float4*)smem;
    float4* u4 = t4 + N / 4;
    float4* v4 = u4 + N / 4;
    __shared__ float red_u[RPB * 8], red_v[RPB * 8];

    const int tid = threadIdx.x;   // 256 threads, 8 warps
    const int wid = tid >> 5;
    const int lane = tid & 31;

    for (int idx = tid; idx < N / 4; idx += 256) {
        t4[idx] = ((const float4*)g_t)[idx];
        u4[idx] = ((const float4*)g_u)[idx];
        v4[idx] = ((const float4*)g_v)[idx];
    }
    __syncthreads();

    const int i0 = blockIdx.x * RPB;
    for (int r = 0; r < RPB; r++) {
        const int i = i0 + r;
        const float thr = -g_s[i];
        const int4* Arow = (const int4*)(A + (long long)i * N);

        int4 a[8];
#pragma unroll
        for (int c = 0; c < 8; c++) a[c] = __ldcs(&Arow[tid + c * 256]);

        float au = 0.f, av = 0.f;
#pragma unroll
        for (int c = 0; c < 8; c++) {
            const int idx = tid + c * 256;
            float4 tt = t4[idx];
            float4 uu = u4[idx];
            float4 vv = v4[idx];
            if (a[c].x) { if (tt.x >= thr) au += uu.x; else av += vv.x; }
            if (a[c].y) { if (tt.y >= thr) au += uu.y; else av += vv.y; }
            if (a[c].z) { if (tt.z >= thr) au += uu.z; else av += vv.z; }
            if (a[c].w) { if (tt.w >= thr) au += uu.w; else av += vv.w; }
        }
#pragma unroll
        for (int o = 16; o; o >>= 1) {
            au += __shfl_xor_sync(0xFFFFFFFFu, au, o);
            av += __shfl_xor_sync(0xFFFFFFFFu, av, o);
        }
        if (lane == 0) { red_u[r * 8 + wid] = au; red_v[r * 8 + wid] = av; }
    }
    __syncthreads();

    if (tid < RPB) {
        const int i = i0 + tid;
        float au = 0.f, av = 0.f;
#pragma unroll
        for (int w = 0; w < 8; w++) { au += red_u[tid * 8 + w]; av += red_v[tid * 8 + w]; }
        const float s = g_s[i];
        const float eu = expf(s);
        const float ev = expf(0.01f * s);
        g_eu[i] = eu;
        g_ev[i] = ev;
        g_den[i] = eu * au + ev * av;
    }
}

// ---------------- K5b: combine numerator tables with denominator ----------------
__global__ void k5b_out(float* __restrict__ out) {
    const int g = blockIdx.x * 256 + threadIdx.x;
    const int i = g >> 6;
    const int f = g & 63;
    const float eu = g_eu[i];
    const float ev = g_ev[i];
    const float den = g_den[i];
    const int k = g_kidx[i];
    const float Tu = g_blkU[NBLK4 * FOUT + f];
    const float pu = g_Pu[k * FOUT + f] + g_blkU[(k >> 6) * FOUT + f];
    const float pv = g_Pv[k * FOUT + f] + g_blkV[(k >> 6) * FOUT + f];
    const float num = eu * (Tu - pu) + ev * pv;
    const float x = num / den;
    out[g] = 1.f / (1.f + expf(-x));
}

// ---------------- stream/event helpers (created once, outside capture) ----------------
static cudaStream_t make_side_stream() {
    cudaStream_t s;
    cudaStreamCreateWithFlags(&s, cudaStreamNonBlocking);
    return s;
}
static cudaEvent_t make_event() {
    cudaEvent_t e;
    cudaEventCreateWithFlags(&e, cudaEventDisableTiming);
    return e;
}

// ---------------- launch ----------------
extern "C" void kernel_launch(void* const* d_in, const int* in_sizes, int n_in,
                              void* d_out, int out_size) {
    (void)in_sizes; (void)n_in; (void)out_size;
    const float* H   = (const float*)d_in[0];
    const int*   A   = (const int*)d_in[1];
    const float* W   = (const float*)d_in[2];
    const float* bW  = (const float*)d_in[3];
    const float* a_w = (const float*)d_in[4];
    const float* a_b = (const float*)d_in[5];
    float* out = (float*)d_out;

    static cudaStream_t s1   = make_side_stream();
    static cudaEvent_t evFork = make_event();
    static cudaEvent_t evJoin = make_event();

    static const int MAIN_SMEM = 3 * N * (int)sizeof(float);  // 96 KB
    cudaFuncSetAttribute(k5a_den, cudaFuncAttributeMaxDynamicSharedMemorySize, MAIN_SMEM);

    // critical path head: GEMM + fused scores
    k1_gemm<<<N / 64, 256>>>(H, W, bW, a_w, a_b);

    // fork: chain B (sort + prefix tables) on side stream
    cudaEventRecord(evFork, 0);
    cudaStreamWaitEvent(s1, evFork, 0);
    ks_minmax<<<1, 1024, 0, s1>>>();
    ks_hist<<<N / 256, 256, 0, s1>>>();
    ks_scan<<<1, 1024, 0, s1>>>();
    ks_scatter<<<N / 256, 256, 0, s1>>>();
    ks_insert<<<NBKT / 256, 256, 0, s1>>>();
    k3b_kidx<<<N / 256, 256, 0, s1>>>();
    k4a_local<<<NBLK4, CHUNK, 0, s1>>>();
    k4b_scan<<<1, 1024, 0, s1>>>();
    cudaEventRecord(evJoin, s1);

    // chain A: heavy HBM-bound denominator scan on main stream (overlaps chain B)
    k5a_den<<<N / RPB, 256, MAIN_SMEM>>>(A);

    // join + combine
    cudaStreamWaitEvent(0, evJoin, 0);
    k5b_out<<<(N * FOUT) / 256, 256>>>(out);
}

// round 15
// speedup vs baseline: 1.3431x; 1.0199x over previous
#include <cuda_runtime.h>
#include <math.h>

#define N     8192
#define FIN   256
#define FOUT  64
#define NBKT  8192   // value buckets for the sort
#define NBLK4 128    // chunks in K4 scan
#define CHUNK 64     // ranks per chunk (NBLK4*CHUNK == N)
#define K5_GRID 456  // 3 blocks/SM * 152 SMs (GB300)

// ---------------- scratch (device globals; no allocations) ----------------
__device__ __align__(16) float g_Wh[N * FOUT];       // H @ W + bW
__device__ __align__(16) float g_s[N];               // s_src + a_b
__device__ __align__(16) float g_t[N];               // s_tar
__device__ __align__(16) float g_u[N];               // exp(t)
__device__ __align__(16) float g_v[N];               // exp(0.01 t)
__device__ __align__(16) float g_ts[N];              // sorted t (ascending)
__device__ __align__(16) int   g_perm[N];            // argsort of t
__device__ __align__(16) int   g_kidx[N];            // lower_bound(ts, -s_i)
__device__ __align__(16) float g_Pu[(N + 1) * FOUT]; // chunk-local exclusive prefix of u*Wh
__device__ __align__(16) float g_Pv[(N + 1) * FOUT]; // chunk-local exclusive prefix of v*Wh
__device__ __align__(16) float g_blkU[(NBLK4 + 1) * FOUT]; // cross-chunk exclusive offsets (+ total)
__device__ __align__(16) float g_blkV[(NBLK4 + 1) * FOUT];
// per-row exponentials / threshold / denominator
__device__ __align__(16) float g_den[N];
__device__ __align__(16) float g_eu[N];   // exp(s)
__device__ __align__(16) float g_ev[N];   // exp(0.01 s)
__device__ __align__(16) float g_thru[N]; // exp(-s)  (u-space threshold)
// sort scratch
__device__ float g_tmin, g_tmax;
__device__ __align__(16) int g_bcnt[NBKT];
__device__ __align__(16) int g_boff[NBKT + 1];
__device__ __align__(16) int g_bfill[NBKT];
__device__ __align__(16) int g_bkt[N];

// ---------------- K1: Wh = H @ W + bW  + fused score epilogue ----------------
__global__ void k1_gemm(const float* __restrict__ H,
                        const float* __restrict__ W,
                        const float* __restrict__ bW,
                        const float* __restrict__ a_w,
                        const float* __restrict__ a_b) {
    __shared__ float As[16][72];
    __shared__ float Bs[16][64];
    const int tid = threadIdx.x;          // 256 threads
    const int tx = tid & 15, ty = tid >> 4;
    const int m0 = blockIdx.x * 64;

    float acc[4][4];
#pragma unroll
    for (int r = 0; r < 4; r++)
#pragma unroll
        for (int c = 0; c < 4; c++) acc[r][c] = 0.f;

    for (int k0 = 0; k0 < FIN; k0 += 16) {
#pragma unroll
        for (int e = 0; e < 4; e++) {
            int li = tid + e * 256;
            int m = li >> 4, kk = li & 15;
            As[kk][m] = H[(m0 + m) * FIN + k0 + kk];
        }
#pragma unroll
        for (int e = 0; e < 4; e++) {
            int li = tid + e * 256;
            int kk = li >> 6, n = li & 63;
            Bs[kk][n] = W[(k0 + kk) * FOUT + n];
        }
        __syncthreads();
#pragma unroll
        for (int kk = 0; kk < 16; kk++) {
            float4 a4 = *(const float4*)&As[kk][ty * 4];
            float4 b4 = *(const float4*)&Bs[kk][tx * 4];
            float av[4] = {a4.x, a4.y, a4.z, a4.w};
            float bv[4] = {b4.x, b4.y, b4.z, b4.w};
#pragma unroll
            for (int r = 0; r < 4; r++)
#pragma unroll
                for (int c = 0; c < 4; c++) acc[r][c] += av[r] * bv[c];
        }
        __syncthreads();
    }

    float bwc[4], a1c[4], a2c[4];
#pragma unroll
    for (int c = 0; c < 4; c++) {
        int n = tx * 4 + c;
        bwc[c] = bW[n];
        a1c[c] = a_w[n];          // source half
        a2c[c] = a_w[FOUT + n];   // target half
    }

    float wh[4][4];
#pragma unroll
    for (int r = 0; r < 4; r++) {
        int m = m0 + ty * 4 + r;
#pragma unroll
        for (int c = 0; c < 4; c++) {
            wh[r][c] = acc[r][c] + bwc[c];
            g_Wh[m * FOUT + tx * 4 + c] = wh[r][c];
        }
    }

    const float ab = a_b[0];
#pragma unroll
    for (int r = 0; r < 4; r++) {
        float ps = 0.f, pt = 0.f;
#pragma unroll
        for (int c = 0; c < 4; c++) {
            ps += wh[r][c] * a1c[c];
            pt += wh[r][c] * a2c[c];
        }
#pragma unroll
        for (int o = 8; o; o >>= 1) {   // xor-reduce within 16-lane group
            ps += __shfl_xor_sync(0xFFFFFFFFu, ps, o);
            pt += __shfl_xor_sync(0xFFFFFFFFu, pt, o);
        }
        if (tx == 0) {
            int i = m0 + ty * 4 + r;
            float s = ps + ab;
            g_s[i] = s;
            g_t[i] = pt;
            g_u[i] = expf(pt);
            g_v[i] = expf(0.01f * pt);
            g_eu[i] = expf(s);
            g_ev[i] = expf(0.01f * s);
            g_thru[i] = expf(-s);
        }
    }
}

// ---------------- Sort stage 1: min/max of t + zero bucket counts ----------------
__global__ void ks_minmax() {
    __shared__ float smn[32], smx[32];
    const int tid = threadIdx.x;  // 1024
    float mn = 3.4e38f, mx = -3.4e38f;
#pragma unroll
    for (int e = 0; e < N / 1024; e++) {
        float v = g_t[tid + e * 1024];
        mn = fminf(mn, v);
        mx = fmaxf(mx, v);
    }
#pragma unroll
    for (int o = 16; o; o >>= 1) {
        mn = fminf(mn, __shfl_xor_sync(0xFFFFFFFFu, mn, o));
        mx = fmaxf(mx, __shfl_xor_sync(0xFFFFFFFFu, mx, o));
    }
    if ((tid & 31) == 0) { smn[tid >> 5] = mn; smx[tid >> 5] = mx; }
    __syncthreads();
    if (tid < 32) {
        mn = smn[tid]; mx = smx[tid];
#pragma unroll
        for (int o = 16; o; o >>= 1) {
            mn = fminf(mn, __shfl_xor_sync(0xFFFFFFFFu, mn, o));
            mx = fmaxf(mx, __shfl_xor_sync(0xFFFFFFFFu, mx, o));
        }
        if (tid == 0) { g_tmin = mn; g_tmax = mx; }
    }
#pragma unroll
    for (int e = 0; e < NBKT / 1024; e++) g_bcnt[tid + e * 1024] = 0;
}

// ---------------- Sort stage 2: histogram ----------------
__global__ void ks_hist() {
    const int i = blockIdx.x * 256 + threadIdx.x;
    const float tmin = g_tmin, tmax = g_tmax;
    const float range = tmax - tmin;
    const float inv = (range > 0.f) ? (float)(NBKT - 1) / range : 0.f;
    float t = g_t[i];
    int b = (int)((t - tmin) * inv);
    b = max(0, min(NBKT - 1, b));
    g_bkt[i] = b;
    atomicAdd(&g_bcnt[b], 1);
}

// ---------------- Sort stage 3: exclusive scan of bucket counts ----------------
__global__ void ks_scan() {
    __shared__ int ssum[1024];
    const int tid = threadIdx.x;  // 1024
    const int base = tid * (NBKT / 1024);   // 8 buckets each
    int c[NBKT / 1024];
    int sum = 0;
#pragma unroll
    for (int e = 0; e < NBKT / 1024; e++) { c[e] = g_bcnt[base + e]; sum += c[e]; }
    ssum[tid] = sum;
    __syncthreads();
    for (int off = 1; off < 1024; off <<= 1) {
        int x = (tid >= off) ? ssum[tid - off] : 0;
        __syncthreads();
        ssum[tid] += x;
        __syncthreads();
    }
    int run = ssum[tid] - sum;  // exclusive
#pragma unroll
    for (int e = 0; e < NBKT / 1024; e++) {
        g_boff[base + e] = run;
        g_bfill[base + e] = run;
        run += c[e];
    }
    if (tid == 1023) g_boff[NBKT] = N;
}

// ---------------- Sort stage 4: scatter into buckets ----------------
__global__ void ks_scatter() {
    const int i = blockIdx.x * 256 + threadIdx.x;
    int b = g_bkt[i];
    int pos = atomicAdd(&g_bfill[b], 1);
    g_ts[pos] = g_t[i];
    g_perm[pos] = i;
}

// ---------------- Sort stage 5: per-bucket insertion sort ----------------
__global__ void ks_insert() {
    const int b = blockIdx.x * 256 + threadIdx.x;
    const int start = g_boff[b];
    const int end = g_boff[b + 1];
    for (int x = start + 1; x < end; x++) {
        float kv = g_ts[x];
        int kp = g_perm[x];
        int y = x - 1;
        while (y >= start && g_ts[y] > kv) {
            g_ts[y + 1] = g_ts[y];
            g_perm[y + 1] = g_perm[y];
            y--;
        }
        g_ts[y + 1] = kv;
        g_perm[y + 1] = kp;
    }
}

// ---------------- K3b: k_i = lower_bound(ts, -s_i), SMEM-staged ----------------
__global__ void k3b_kidx() {
    __shared__ float sts[N];  // 32KB
    const int tid = threadIdx.x;  // 256
    for (int idx = tid; idx < N / 4; idx += 256)
        ((float4*)sts)[idx] = ((const float4*)g_ts)[idx];
    __syncthreads();
    const int i = blockIdx.x * 256 + tid;
    const float thr = -g_s[i];
    int lo = 0, hi = N;
    while (lo < hi) {
        int mid = (lo + hi) >> 1;
        if (sts[mid] < thr) lo = mid + 1; else hi = mid;
    }
    g_kidx[i] = lo;
}

// ---------------- K4a: chunk-local exclusive prefixes (coalesced) ----------------
__global__ void k4a_local() {
    __shared__ int   sp[CHUNK];
    __shared__ float su[CHUNK], sv[CHUNK];
    const int tid = threadIdx.x;          // 64 threads, tid == feature
    const int r0 = blockIdx.x * CHUNK;
    {
        int p = g_perm[r0 + tid];
        sp[tid] = p;
        su[tid] = g_u[p];
        sv[tid] = g_v[p];
    }
    __syncthreads();
    float ru = 0.f, rv = 0.f;
#pragma unroll 8
    for (int e = 0; e < CHUNK; e++) {
        int p = sp[e];
        float wh = __ldg(&g_Wh[p * FOUT + tid]);
        g_Pu[(r0 + e) * FOUT + tid] = ru;
        g_Pv[(r0 + e) * FOUT + tid] = rv;
        ru += su[e] * wh;
        rv += sv[e] * wh;
    }
    g_blkU[blockIdx.x * FOUT + tid] = ru;   // raw chunk totals (scanned by k4b)
    g_blkV[blockIdx.x * FOUT + tid] = rv;
}

// ---------------- K4b: cross-chunk exclusive scan (in SMEM) ----------------
__global__ void k4b_scan() {
    __shared__ float s[NBLK4 * FOUT];  // 32KB
    const int tid = threadIdx.x;       // 1024
#pragma unroll
    for (int pass = 0; pass < 2; pass++) {
        float* arr = pass ? g_blkV : g_blkU;
#pragma unroll
        for (int e = 0; e < (NBLK4 * FOUT) / 1024; e++)
            s[tid + e * 1024] = arr[tid + e * 1024];
        __syncthreads();
        for (int off = 1; off < NBLK4; off <<= 1) {
            float tmp[(NBLK4 * FOUT) / 1024];
#pragma unroll
            for (int e = 0; e < (NBLK4 * FOUT) / 1024; e++) {
                int idx = tid + e * 1024;
                int b = idx >> 6;
                tmp[e] = (b >= off) ? s[idx - off * FOUT] : 0.f;
            }
            __syncthreads();
#pragma unroll
            for (int e = 0; e < (NBLK4 * FOUT) / 1024; e++)
                s[tid + e * 1024] += tmp[e];
            __syncthreads();
        }
#pragma unroll
        for (int e = 0; e < (NBLK4 * FOUT) / 1024; e++) {
            int idx = tid + e * 1024;
            int b = idx >> 6;
            arr[idx] = (b > 0) ? s[idx - FOUT] : 0.f;
        }
        if (tid < FOUT) {
            arr[NBLK4 * FOUT + tid] = s[(NBLK4 - 1) * FOUT + tid];
            if (pass == 0) g_Pu[N * FOUT + tid] = 0.f;
            else           g_Pv[N * FOUT + tid] = 0.f;
        }
        __syncthreads();
    }
}

// ---------------- K5a: persistent A-masked denominator scan ----------------
// 64KB dyn smem (u,v), 3 blocks/SM, u-space threshold (no t array).
__global__ void __launch_bounds__(256, 3) k5a_den(const int* __restrict__ A) {
    extern __shared__ float smem[];
    float4* u4 = (float4*)smem;          // N/4 float4 (32KB)
    float4* v4 = u4 + N / 4;             // 32KB
    __shared__ float red_u[2][8], red_v[2][8];

    const int tid = threadIdx.x;   // 256 threads, 8 warps
    const int wid = tid >> 5;
    const int lane = tid & 31;

    for (int idx = tid; idx < N / 4; idx += 256) {
        u4[idx] = ((const float4*)g_u)[idx];
        v4[idx] = ((const float4*)g_v)[idx];
    }
    __syncthreads();

    int par = 0;
    for (int i = blockIdx.x; i < N; i += gridDim.x) {
        const float thr = g_thru[i];
        const int4* Arow = (const int4*)(A + (long long)i * N);

        int4 a[8];
#pragma unroll
        for (int c = 0; c < 8; c++) a[c] = __ldcs(&Arow[tid + c * 256]);

        float au = 0.f, av = 0.f;
#pragma unroll
        for (int c = 0; c < 8; c++) {
            const int idx = tid + c * 256;
            float4 uu = u4[idx];
            float4 vv = v4[idx];
            if (a[c].x) { if (uu.x >= thr) au += uu.x; else av += vv.x; }
            if (a[c].y) { if (uu.y >= thr) au += uu.y; else av += vv.y; }
            if (a[c].z) { if (uu.z >= thr) au += uu.z; else av += vv.z; }
            if (a[c].w) { if (uu.w >= thr) au += uu.w; else av += vv.w; }
        }
#pragma unroll
        for (int o = 16; o; o >>= 1) {
            au += __shfl_xor_sync(0xFFFFFFFFu, au, o);
            av += __shfl_xor_sync(0xFFFFFFFFu, av, o);
        }
        if (lane == 0) { red_u[par][wid] = au; red_v[par][wid] = av; }
        __syncthreads();
        if (tid == 0) {
            float su = 0.f, sv = 0.f;
#pragma unroll
            for (int w = 0; w < 8; w++) { su += red_u[par][w]; sv += red_v[par][w]; }
            g_den[i] = g_eu[i] * su + g_ev[i] * sv;
        }
        par ^= 1;   // double-buffered partials: one sync per row
    }
}

// ---------------- K5b: combine numerator tables with denominator ----------------
__global__ void k5b_out(float* __restrict__ out) {
    const int g = blockIdx.x * 256 + threadIdx.x;
    const int i = g >> 6;
    const int f = g & 63;
    const float eu = g_eu[i];
    const float ev = g_ev[i];
    const float den = g_den[i];
    const int k = g_kidx[i];
    const float Tu = g_blkU[NBLK4 * FOUT + f];
    const float pu = g_Pu[k * FOUT + f] + g_blkU[(k >> 6) * FOUT + f];
    const float pv = g_Pv[k * FOUT + f] + g_blkV[(k >> 6) * FOUT + f];
    const float num = eu * (Tu - pu) + ev * pv;
    const float x = num / den;
    out[g] = 1.f / (1.f + expf(-x));
}

// ---------------- stream/event helpers (created once, outside capture) ----------------
static cudaStream_t make_side_stream() {
    cudaStream_t s;
    cudaStreamCreateWithFlags(&s, cudaStreamNonBlocking);
    return s;
}
static cudaEvent_t make_event() {
    cudaEvent_t e;
    cudaEventCreateWithFlags(&e, cudaEventDisableTiming);
    return e;
}

// ---------------- launch ----------------
extern "C" void kernel_launch(void* const* d_in, const int* in_sizes, int n_in,
                              void* d_out, int out_size) {
    (void)in_sizes; (void)n_in; (void)out_size;
    const float* H   = (const float*)d_in[0];
    const int*   A   = (const int*)d_in[1];
    const float* W   = (const float*)d_in[2];
    const float* bW  = (const float*)d_in[3];
    const float* a_w = (const float*)d_in[4];
    const float* a_b = (const float*)d_in[5];
    float* out = (float*)d_out;

    static cudaStream_t s1   = make_side_stream();
    static cudaEvent_t evFork = make_event();
    static cudaEvent_t evJoin = make_event();

    static const int MAIN_SMEM = 2 * N * (int)sizeof(float);  // 64 KB
    cudaFuncSetAttribute(k5a_den, cudaFuncAttributeMaxDynamicSharedMemorySize, MAIN_SMEM);

    // critical path head: GEMM + fused scores/exponentials
    k1_gemm<<<N / 64, 256>>>(H, W, bW, a_w, a_b);

    // fork: chain B (sort + prefix tables) on side stream
    cudaEventRecord(evFork, 0);
    cudaStreamWaitEvent(s1, evFork, 0);
    ks_minmax<<<1, 1024, 0, s1>>>();
    ks_hist<<<N / 256, 256, 0, s1>>>();
    ks_scan<<<1, 1024, 0, s1>>>();
    ks_scatter<<<N / 256, 256, 0, s1>>>();
    ks_insert<<<NBKT / 256, 256, 0, s1>>>();
    k3b_kidx<<<N / 256, 256, 0, s1>>>();
    k4a_local<<<NBLK4, CHUNK, 0, s1>>>();
    k4b_scan<<<1, 1024, 0, s1>>>();
    cudaEventRecord(evJoin, s1);

    // chain A: heavy HBM-bound denominator scan (persistent, 3 blocks/SM)
    k5a_den<<<K5_GRID, 256, MAIN_SMEM>>>(A);

    // join + combine
    cudaStreamWaitEvent(0, evJoin, 0);
    k5b_out<<<(N * FOUT) / 256, 256>>>(out);
}